// round 8
// baseline (speedup 1.0000x reference)
#include <cuda_runtime.h>
#include <cstdint>

#define NUM_NODES 500000
#define D 128
#define U 32
#define T 4
#define A 32
#define N_SRC 65536
#define B 8192
#define E 262144
#define BB 16  // batch rows per att block

typedef unsigned long long ull;

#define FMA_F32X2(d, a, b, c) \
    asm("fma.rn.f32x2 %0, %1, %2, %3;" : "=l"(d) : "l"(a), "l"(b), "l"(c))
#define PACK_DUP_F32X2(d, s) \
    asm("mov.b64 %0, {%1, %1};" : "=l"(d) : "f"(s))
#define PACK_F32X2(d, lo, hi) \
    asm("mov.b64 %0, {%1, %2};" : "=l"(d) : "f"(lo), "f"(hi))
#define UNPACK_F32X2(lo, hi, s) \
    asm("mov.b64 {%0, %1}, %2;" : "=f"(lo), "=f"(hi) : "l"(s))

// Scratch: agg[b][t][u] (4 MB) and comb[b][u] (1 MB)
__device__ float g_agg[B * T * U];
__device__ float g_comb[B * U];

// ---------------------------------------------------------------------------
// Kernel 1: edge aggregation (push, red.v4) — unchanged, at its L2 floor.
// ---------------------------------------------------------------------------
__global__ __launch_bounds__(256) void edge_agg_kernel(
    const float* __restrict__ nte_tab,
    const int* __restrict__ input_nodes,
    const int* __restrict__ edge_src,
    const int* __restrict__ edge_dst) {
    const int t   = blockIdx.y;
    const int e0  = blockIdx.x * 64 + (threadIdx.x >> 3);
    const int e1  = e0 + 32;
    const int sub = threadIdx.x & 7;

    const int src0 = __ldg(&edge_src[t * E + e0]);
    const int src1 = __ldg(&edge_src[t * E + e1]);
    const int dst0 = __ldg(&edge_dst[t * E + e0]);
    const int dst1 = __ldg(&edge_dst[t * E + e1]);
    const int n0   = __ldg(&input_nodes[src0]);
    const int n1   = __ldg(&input_nodes[src1]);

    const float4 v0 = __ldg((const float4*)nte_tab + (size_t)(n0 * T + t) * (U / 4) + sub);
    const float4 v1 = __ldg((const float4*)nte_tab + (size_t)(n1 * T + t) * (U / 4) + sub);

    float* p0 = g_agg + ((size_t)dst0 * T + t) * U + sub * 4;
    float* p1 = g_agg + ((size_t)dst1 * T + t) * U + sub * 4;
    asm volatile("red.global.add.v4.f32 [%0], {%1,%2,%3,%4};"
                 :: "l"(p0), "f"(v0.x), "f"(v0.y), "f"(v0.z), "f"(v0.w) : "memory");
    asm volatile("red.global.add.v4.f32 [%0], {%1,%2,%3,%4};"
                 :: "l"(p1), "f"(v1.x), "f"(v1.y), "f"(v1.z), "f"(v1.w) : "memory");
}

// ---------------------------------------------------------------------------
// Kernel 2: attention scores + softmax + combine -> g_comb[B][U].
// BB=16 rows/block, 256 threads; warp w: t = w&3, rows (w>>2)*8 .. +7.
// Softmax folded into the combine loop (no separate phase/barrier).
// ---------------------------------------------------------------------------
__global__ __launch_bounds__(256) void att_kernel(
    const float* __restrict__ ws1,          // [T][U][A]
    const float* __restrict__ ws2)          // [T][A]
{
    __shared__ float nte_s[BB][T * U];      // 8 KB
    __shared__ float scores_s[BB][T];

    const int b0   = blockIdx.x * BB;
    const int tid  = threadIdx.x;
    const int lane = tid & 31;
    const int warp = tid >> 5;
    const int t    = warp & 3;
    const int bbase = (warp >> 2) * 8;

    // Load nte (8 KB contiguous from L2)
    {
        const float4* s4 = (const float4*)(g_agg + (size_t)b0 * T * U);
        float4* d4 = (float4*)&nte_s[0][0];
        #pragma unroll
        for (int i = tid; i < BB * T * U / 4; i += 256) d4[i] = s4[i];
    }
    __syncthreads();

    // Stage A: scores
    {
        float w1r[U];
        #pragma unroll
        for (int u = 0; u < U; u++) w1r[u] = __ldg(&ws1[(t * U + u) * A + lane]);
        const float w2r = __ldg(&ws2[t * A + lane]);

        #pragma unroll
        for (int i = 0; i < 8; i++) {
            const int bb = bbase + i;
            float acc = 0.f;
            #pragma unroll
            for (int u = 0; u < U; u++) acc += nte_s[bb][t * U + u] * w1r[u];
            float sc = tanhf(acc) * w2r;
            #pragma unroll
            for (int o = 16; o; o >>= 1) sc += __shfl_xor_sync(0xFFFFFFFFu, sc, o);
            if (lane == 0) scores_s[bb][t] = sc;
        }
    }
    __syncthreads();

    // Combine with inline softmax; write comb to global.
    #pragma unroll
    for (int i = tid; i < BB * U; i += 256) {
        const int bb = i >> 5, u = i & 31;
        const float s0 = scores_s[bb][0], s1 = scores_s[bb][1];
        const float s2 = scores_s[bb][2], s3 = scores_s[bb][3];
        const float m  = fmaxf(fmaxf(s0, s1), fmaxf(s2, s3));
        const float e0 = __expf(s0 - m), e1 = __expf(s1 - m);
        const float e2 = __expf(s2 - m), e3 = __expf(s3 - m);
        const float inv = 1.f / (e0 + e1 + e2 + e3);
        const float c = (e0 * nte_s[bb][0 * U + u] + e1 * nte_s[bb][1 * U + u] +
                         e2 * nte_s[bb][2 * U + u] + e3 * nte_s[bb][3 * U + u]) * inv;
        g_comb[(size_t)(b0 + bb) * U + u] = c;
    }
}

// ---------------------------------------------------------------------------
// Kernel 3: out[b,t,:] = normalize(node_emb[out_nodes[b],:] + comb[b] @ w[t])
// Barrier-free. One warp = (t, 4 batch rows); lane owns a float4 of D.
// comb rows in registers, broadcast via shfl; weights loaded once per 4 rows.
// ---------------------------------------------------------------------------
__global__ __launch_bounds__(256, 6) void out_kernel(
    const float* __restrict__ node_emb,     // [NUM_NODES][D]
    const float* __restrict__ w,            // [T][U][D]
    const int*  __restrict__ out_nodes,     // [B]
    float*      __restrict__ out)           // [B][T][D]
{
    const int lane = threadIdx.x & 31;
    const int gw   = blockIdx.x * 8 + (threadIdx.x >> 5);   // 0..8191
    const int t    = gw & 3;
    const int b0   = (gw >> 2) * 4;                         // 4 rows per warp

    // comb rows in registers: cr[j] holds comb[b0+j][lane]
    float cr[4];
    #pragma unroll
    for (int j = 0; j < 4; j++) cr[j] = __ldg(&g_comb[(size_t)(b0 + j) * U + lane]);

    ull acc[4][2];
    #pragma unroll
    for (int j = 0; j < 4; j++) { acc[j][0] = 0; acc[j][1] = 0; }

    const float4* wbase = (const float4*)w + (size_t)t * U * (D / 4) + lane;
    #pragma unroll
    for (int u = 0; u < U; u++) {
        const float4 wv = __ldg(&wbase[u * (D / 4)]);
        ull wlo, whi;
        PACK_F32X2(wlo, wv.x, wv.y);
        PACK_F32X2(whi, wv.z, wv.w);
        #pragma unroll
        for (int j = 0; j < 4; j++) {
            const float c = __shfl_sync(0xFFFFFFFFu, cr[j], u);
            ull c2;
            PACK_DUP_F32X2(c2, c);
            FMA_F32X2(acc[j][0], c2, wlo, acc[j][0]);
            FMA_F32X2(acc[j][1], c2, whi, acc[j][1]);
        }
    }

    #pragma unroll
    for (int j = 0; j < 4; j++) {
        const int b = b0 + j;
        float4 o;
        UNPACK_F32X2(o.x, o.y, acc[j][0]);
        UNPACK_F32X2(o.z, o.w, acc[j][1]);

        const int nidx = __ldg(&out_nodes[b]);
        const float4 nv = __ldg((const float4*)node_emb + (size_t)nidx * (D / 4) + lane);
        o.x += nv.x; o.y += nv.y; o.z += nv.z; o.w += nv.w;

        float ss = o.x * o.x + o.y * o.y + o.z * o.z + o.w * o.w;
        #pragma unroll
        for (int off = 16; off; off >>= 1) ss += __shfl_xor_sync(0xFFFFFFFFu, ss, off);

        const float scale = 1.f / fmaxf(sqrtf(ss), 1e-12f);
        o.x *= scale; o.y *= scale; o.z *= scale; o.w *= scale;

        ((float4*)out)[(size_t)(b * T + t) * (D / 4) + lane] = o;
    }
}

// ---------------------------------------------------------------------------
// Launch
// ---------------------------------------------------------------------------
extern "C" void kernel_launch(void* const* d_in, const int* in_sizes, int n_in,
                              void* d_out, int out_size) {
    const float* node_emb     = (const float*)d_in[0];  // [500000][128]
    const float* nte_tab      = (const float*)d_in[1];  // [500000][4][32]
    const float* trans_w      = (const float*)d_in[2];  // [4][32][128]
    const float* trans_w_s1   = (const float*)d_in[3];  // [4][32][32]
    const float* trans_w_s2   = (const float*)d_in[4];  // [4][32][1]
    const int*   input_nodes  = (const int*)d_in[5];    // [65536]
    const int*   output_nodes = (const int*)d_in[6];    // [8192]
    const int*   edge_src     = (const int*)d_in[7];    // [4][262144]
    const int*   edge_dst     = (const int*)d_in[8];    // [4][262144]
    float*       out          = (float*)d_out;          // [8192][4][128]

    void* agg_ptr = nullptr;
    cudaGetSymbolAddress(&agg_ptr, g_agg);
    cudaMemsetAsync(agg_ptr, 0, (size_t)B * T * U * sizeof(float));

    dim3 grid_e(E / 64, T);
    edge_agg_kernel<<<grid_e, 256>>>(nte_tab, input_nodes, edge_src, edge_dst);

    att_kernel<<<B / BB, 256>>>(trans_w_s1, trans_w_s2);

    out_kernel<<<(B * T) / 32, 256>>>(node_emb, trans_w, output_nodes, out);
}